// round 12
// baseline (speedup 1.0000x reference)
#include <cuda_runtime.h>
#include <cstdint>

#define BATCH 16
#define NV    20000
#define FIN   64
#define COUT  64
#define KNB   16

#define GEMM_PER_B   157                 // ceil(20000/128)
#define GATHER_PER_B 625                 // 20000/32
#define STAGE_BLKS   (GEMM_PER_B + GATHER_PER_B)
#define TOTAL_BLKS   (STAGE_BLKS * BATCH)

// Scratch: y = x @ Wn with a zero pad row at index 0.  [B][V+1][COUT]
__device__ float g_y[(size_t)BATCH * (NV + 1) * COUT];
// Weights in mma-fragment order: [mat(2)][ks(8)][nt(8)][lane(32)][2] tf32 bits
__device__ uint32_t g_wfrag[2 * 8 * 8 * 32 * 2];
// Per-batch GEMM completion counters (device-side dependency).
__device__ unsigned int g_done[BATCH];

// ---------------------------------------------------------------------------
// Pre-kernel: swizzle Wx/Wn into fragment order, zero y pad rows + counters.
// ---------------------------------------------------------------------------
__global__ void wfrag_build_kernel(const float* __restrict__ Wx,
                                   const float* __restrict__ Wn)
{
    int i = blockIdx.x * 256 + threadIdx.x;        // 0..16383
    int j    =  i        & 1;
    int lane = (i >> 1)  & 31;
    int nt   = (i >> 6)  & 7;
    int ks   = (i >> 9)  & 7;
    int mat  =  i >> 12;
    int k = (lane & 3) + 4 * j + 8 * ks;
    int n = (lane >> 2) + 8 * nt;
    const float* W = mat ? Wn : Wx;
    float v = W[k * COUT + n];
    uint32_t tv;
    asm("cvt.rna.tf32.f32 %0, %1;" : "=r"(tv) : "f"(v));
    g_wfrag[i] = tv;

    if (i < BATCH * COUT) {                        // zero y pad rows
        int b = i >> 6;
        int c = i & 63;
        g_y[(size_t)b * (NV + 1) * COUT + c] = 0.f;
    }
    if (i < BATCH) g_done[i] = 0u;                 // reset counters (replay-safe)
}

// ---------------------------------------------------------------------------
// Fused pipeline kernel, single launch. Stage s = batch s:
//   blocks [s*782, s*782+157)   : GEMM batch s   -> releases g_done[s]
//   blocks [s*782+157, s*782+782): gather batch s -> acquires g_done[s]
// Block dispatch is monotonic over the queue, so a resident gather CTA's
// producer CTAs are always already dispatched -> spin terminates.
// ---------------------------------------------------------------------------
__global__ __launch_bounds__(256)
void pipeline_kernel(const float* __restrict__ x,
                     const float* __restrict__ bias,
                     const int*   __restrict__ neighbor,
                     float*       __restrict__ out)
{
    __shared__ uint32_t sW[2 * 8 * 8 * 32 * 2];    // 32 KB (GEMM role)
    __shared__ int      sN[512];                   // 2 KB  (gather role)

    const int tid = threadIdx.x;
    const int b   = blockIdx.x / STAGE_BLKS;       // batch
    const int rem = blockIdx.x % STAGE_BLKS;

    if (rem < GEMM_PER_B) {
        // ================= GEMM role: batch b ===============================
        // Stage fragment-ordered weights: 2048 uint4, coalesced.
        {
            const uint4* src = (const uint4*)g_wfrag;
            uint4*       dst = (uint4*)sW;
            #pragma unroll
            for (int i = 0; i < 8; ++i)
                dst[tid + i * 256] = src[tid + i * 256];
        }
        __syncthreads();

        const int lane = tid & 31;
        const int wid  = tid >> 5;
        const int g    = lane >> 2;
        const int t    = lane & 3;
        const int vb   = rem * 128 + wid * 16;
        const int r0   = vb + g;
        const int r1   = r0 + 8;

        const float* __restrict__ xb = x + (size_t)b * NV * FIN;

        // Prefetch A: 2 rows x 16 cols. 32 independent LDG.32.
        float f0[16], f1[16];
        #pragma unroll
        for (int j = 0; j < 16; ++j) {
            int c = t + 4 * j;
            f0[j] = (r0 < NV) ? __ldg(&xb[(size_t)r0 * FIN + c]) : 0.f;
            f1[j] = (r1 < NV) ? __ldg(&xb[(size_t)r1 * FIN + c]) : 0.f;
        }
        uint32_t ar0[16], ar1[16];
        #pragma unroll
        for (int j = 0; j < 16; ++j) {
            asm("cvt.rna.tf32.f32 %0, %1;" : "=r"(ar0[j]) : "f"(f0[j]));
            asm("cvt.rna.tf32.f32 %0, %1;" : "=r"(ar1[j]) : "f"(f1[j]));
        }

        float accX[8][4] = {{0.f}};
        float accN[8][4] = {{0.f}};

        #pragma unroll
        for (int ks = 0; ks < 8; ++ks) {
            const uint32_t a0 = ar0[2 * ks];
            const uint32_t a1 = ar1[2 * ks];
            const uint32_t a2 = ar0[2 * ks + 1];
            const uint32_t a3 = ar1[2 * ks + 1];

            #pragma unroll
            for (int nt = 0; nt < 8; ++nt) {
                const uint2 bx = *(const uint2*)&sW[((0 * 8 + ks) * 8 + nt) * 64 + lane * 2];
                const uint2 bn = *(const uint2*)&sW[((1 * 8 + ks) * 8 + nt) * 64 + lane * 2];

                asm volatile(
                    "mma.sync.aligned.m16n8k8.row.col.f32.tf32.tf32.f32 "
                    "{%0,%1,%2,%3}, {%4,%5,%6,%7}, {%8,%9}, {%0,%1,%2,%3};"
                    : "+f"(accX[nt][0]), "+f"(accX[nt][1]),
                      "+f"(accX[nt][2]), "+f"(accX[nt][3])
                    : "r"(a0), "r"(a1), "r"(a2), "r"(a3),
                      "r"(bx.x), "r"(bx.y));
                asm volatile(
                    "mma.sync.aligned.m16n8k8.row.col.f32.tf32.tf32.f32 "
                    "{%0,%1,%2,%3}, {%4,%5,%6,%7}, {%8,%9}, {%0,%1,%2,%3};"
                    : "+f"(accN[nt][0]), "+f"(accN[nt][1]),
                      "+f"(accN[nt][2]), "+f"(accN[nt][3])
                    : "r"(a0), "r"(a1), "r"(a2), "r"(a3),
                      "r"(bn.x), "r"(bn.y));
            }
        }

        float* __restrict__ outb = out + (size_t)b * NV * COUT;
        float* __restrict__ yb   = g_y + (size_t)b * (NV + 1) * COUT;
        #pragma unroll
        for (int nt = 0; nt < 8; ++nt) {
            const int c = nt * 8 + 2 * t;
            const float2 bv = *(const float2*)&bias[c];
            if (r0 < NV) {
                *(float2*)&outb[(size_t)r0 * COUT + c] =
                    make_float2(accX[nt][0] + bv.x, accX[nt][1] + bv.y);
                *(float2*)&yb[(size_t)(r0 + 1) * COUT + c] =
                    make_float2(accN[nt][0], accN[nt][1]);
            }
            if (r1 < NV) {
                *(float2*)&outb[(size_t)r1 * COUT + c] =
                    make_float2(accX[nt][2] + bv.x, accX[nt][3] + bv.y);
                *(float2*)&yb[(size_t)(r1 + 1) * COUT + c] =
                    make_float2(accN[nt][2], accN[nt][3]);
            }
        }

        // Release: all stores visible, then count this CTA done.
        __threadfence();
        __syncthreads();
        if (tid == 0) atomicAdd(&g_done[b], 1u);
    } else {
        // ================= Gather role: batch b =============================
        const int blk  = rem - GEMM_PER_B;
        const int warp = tid >> 5;
        const int lane = tid & 31;
        const int half = lane >> 4;          // 0 = even-k rows, 1 = odd-k rows
        const int l16  = lane & 15;
        const int vblk = blk * 32;
        const int v0   = vblk + warp * 4;

        // Stage neighbor ids while (possibly) waiting on the producer.
        ((int2*)sN)[tid] = __ldg((const int2*)&neighbor[vblk * KNB] + tid);

        // Acquire: wait until all GEMM CTAs of this batch completed.
        if (tid == 0) {
            unsigned ns = 8;
            while (atomicAdd(&g_done[b], 0u) < (unsigned)GEMM_PER_B) {
                __nanosleep(ns);
                if (ns < 1024) ns <<= 1;
            }
            __threadfence();
        }
        __syncthreads();

        const float* __restrict__ yb = g_y + (size_t)b * (NV + 1) * COUT;

        float4 acc0 = make_float4(0.f, 0.f, 0.f, 0.f);
        float4 acc1 = acc0, acc2 = acc0, acc3 = acc0;

        const int2* ids = (const int2*)&sN[warp * 4 * KNB];

        #pragma unroll
        for (int p = 0; p < 8; ++p) {
            const int2 i0 = ids[0 * 8 + p];          // uniform LDS.64 broadcast
            const int2 i1 = ids[1 * 8 + p];
            const int2 i2 = ids[2 * 8 + p];
            const int2 i3 = ids[3 * 8 + p];
            const int r0 = half ? i0.y : i0.x;       // id; 0 = zero pad row
            const int r1 = half ? i1.y : i1.x;
            const int r2 = half ? i2.y : i2.x;
            const int r3 = half ? i3.y : i3.x;

            const float4 t0 = *(const float4*)(yb + (size_t)r0 * COUT + l16 * 4);
            const float4 t1 = *(const float4*)(yb + (size_t)r1 * COUT + l16 * 4);
            const float4 t2 = *(const float4*)(yb + (size_t)r2 * COUT + l16 * 4);
            const float4 t3 = *(const float4*)(yb + (size_t)r3 * COUT + l16 * 4);

            acc0.x += t0.x; acc0.y += t0.y; acc0.z += t0.z; acc0.w += t0.w;
            acc1.x += t1.x; acc1.y += t1.y; acc1.z += t1.z; acc1.w += t1.w;
            acc2.x += t2.x; acc2.y += t2.y; acc2.z += t2.z; acc2.w += t2.w;
            acc3.x += t3.x; acc3.y += t3.y; acc3.z += t3.z; acc3.w += t3.w;
        }

        // Combine even/odd halves: butterfly across lane 16.
        #pragma unroll
        for (int c = 0; c < 4; ++c) {
            ((float*)&acc0)[c] += __shfl_xor_sync(0xffffffffu, ((float*)&acc0)[c], 16);
            ((float*)&acc1)[c] += __shfl_xor_sync(0xffffffffu, ((float*)&acc1)[c], 16);
            ((float*)&acc2)[c] += __shfl_xor_sync(0xffffffffu, ((float*)&acc2)[c], 16);
            ((float*)&acc3)[c] += __shfl_xor_sync(0xffffffffu, ((float*)&acc3)[c], 16);
        }

        // Pairwise RMW: low half -> v0+0 / v0+2, high half -> v0+1 / v0+3.
        const float s = 1.0f / (float)KNB;
        const float4 sAB = half ? acc1 : acc0;
        const float4 sCD = half ? acc3 : acc2;

        float* opAB = out + ((size_t)b * NV + v0 + half)     * COUT + l16 * 4;
        float* opCD = out + ((size_t)b * NV + v0 + 2 + half) * COUT + l16 * 4;

        float4 oAB = *(const float4*)opAB;
        float4 oCD = *(const float4*)opCD;
        oAB.x += sAB.x * s; oAB.y += sAB.y * s; oAB.z += sAB.z * s; oAB.w += sAB.w * s;
        oCD.x += sCD.x * s; oCD.y += sCD.y * s; oCD.z += sCD.z * s; oCD.w += sCD.w * s;
        *(float4*)opAB = oAB;
        *(float4*)opCD = oCD;
    }
}

extern "C" void kernel_launch(void* const* d_in, const int* in_sizes, int n_in,
                              void* d_out, int out_size)
{
    // metadata order: x, Wx, Wn, b, neighbor
    const float* x        = (const float*)d_in[0];
    const float* Wx       = (const float*)d_in[1];
    const float* Wn       = (const float*)d_in[2];
    const float* bias     = (const float*)d_in[3];
    const int*   neighbor = (const int*)d_in[4];
    float*       out      = (float*)d_out;

    wfrag_build_kernel<<<64, 256>>>(Wx, Wn);
    pipeline_kernel<<<TOTAL_BLKS, 256>>>(x, bias, neighbor, out);
}

// round 13
// speedup vs baseline: 1.6178x; 1.6178x over previous
#include <cuda_runtime.h>
#include <cstdint>

#define BATCH 16
#define NV    20000
#define FIN   64
#define COUT  64
#define KNB   16

// Scratch: y = x @ Wn with a zero pad row at index 0.  [B][V+1][COUT]
__device__ float g_y[(size_t)BATCH * (NV + 1) * COUT];
// Weights in mma-fragment order: [mat(2)][ks(8)][nt(8)][lane(32)][2] tf32 bits
__device__ uint32_t g_wfrag[2 * 8 * 8 * 32 * 2];

// ---------------------------------------------------------------------------
// Pre-kernel: swizzle Wx/Wn into m16n8k8 B-fragment order (tf32),
// and zero the pad rows of g_y (row 0 of each batch).
// ---------------------------------------------------------------------------
__global__ void wfrag_build_kernel(const float* __restrict__ Wx,
                                   const float* __restrict__ Wn)
{
    int i = blockIdx.x * 256 + threadIdx.x;        // 0..16383
    int j    =  i        & 1;
    int lane = (i >> 1)  & 31;
    int nt   = (i >> 6)  & 7;
    int ks   = (i >> 9)  & 7;
    int mat  =  i >> 12;
    int k = (lane & 3) + 4 * j + 8 * ks;
    int n = (lane >> 2) + 8 * nt;
    const float* W = mat ? Wn : Wx;
    float v = W[k * COUT + n];
    uint32_t tv;
    asm("cvt.rna.tf32.f32 %0, %1;" : "=r"(tv) : "f"(v));
    g_wfrag[i] = tv;

    // Zero pad rows: 16 batches * 64 channels = 1024 floats
    if (i < BATCH * COUT) {
        int b = i >> 6;
        int c = i & 63;
        g_y[(size_t)b * (NV + 1) * COUT + c] = 0.f;
    }
}

// ---------------------------------------------------------------------------
// Kernel A: tensor-core dual GEMM. out = x@Wx + b (d_out), y = x@Wn (scratch)
// CTA = 128 verts x 64 cols, 8 warps; warp = 16 verts x 64 cols, K=64.
// Mainloop split into two nt-halves (32 live acc regs) -> 3 CTAs/SM.
// ---------------------------------------------------------------------------
__global__ __launch_bounds__(256, 3)
void gemm_tc_kernel(const float* __restrict__ x,
                    const float* __restrict__ bias,
                    float*       __restrict__ out)
{
    __shared__ uint32_t sW[2 * 8 * 8 * 32 * 2];    // 32 KB

    const int tid = threadIdx.x;

    // Stage fragment-ordered weights: 2048 uint4, 8 per thread, coalesced.
    {
        const uint4* src = (const uint4*)g_wfrag;
        uint4*       dst = (uint4*)sW;
        #pragma unroll
        for (int i = 0; i < 8; ++i)
            dst[tid + i * 256] = src[tid + i * 256];
    }
    __syncthreads();

    const int lane = tid & 31;
    const int wid  = tid >> 5;
    const int g    = lane >> 2;      // group id (row within m-tile)
    const int t    = lane & 3;       // thread-in-group (col phase)
    const int b    = blockIdx.y;
    const int vb   = blockIdx.x * 128 + wid * 16;
    const int r0   = vb + g;
    const int r1   = r0 + 8;

    const float* __restrict__ xb = x + (size_t)b * NV * FIN;

    // ---- Prefetch A: 2 rows x 16 cols (cols == t mod 4). 32 indep LDG.32 --
    float f0[16], f1[16];
    #pragma unroll
    for (int j = 0; j < 16; ++j) {
        int c = t + 4 * j;
        f0[j] = (r0 < NV) ? __ldg(&xb[(size_t)r0 * FIN + c]) : 0.f;
        f1[j] = (r1 < NV) ? __ldg(&xb[(size_t)r1 * FIN + c]) : 0.f;
    }
    uint32_t ar0[16], ar1[16];
    #pragma unroll
    for (int j = 0; j < 16; ++j) {
        asm("cvt.rna.tf32.f32 %0, %1;" : "=r"(ar0[j]) : "f"(f0[j]));
        asm("cvt.rna.tf32.f32 %0, %1;" : "=r"(ar1[j]) : "f"(f1[j]));
    }

    float* __restrict__ outb = out + (size_t)b * NV * COUT;
    float* __restrict__ yb   = g_y + (size_t)b * (NV + 1) * COUT;

    // ---- Two nt-halves: 32 live accumulator regs each, epilogue per half --
    #pragma unroll
    for (int h = 0; h < 2; ++h) {
        float accX[4][4] = {{0.f}};
        float accN[4][4] = {{0.f}};

        #pragma unroll
        for (int ks = 0; ks < 8; ++ks) {
            const uint32_t a0 = ar0[2 * ks];
            const uint32_t a1 = ar1[2 * ks];
            const uint32_t a2 = ar0[2 * ks + 1];
            const uint32_t a3 = ar1[2 * ks + 1];

            #pragma unroll
            for (int q = 0; q < 4; ++q) {
                const int nt = h * 4 + q;
                const uint2 bx = *(const uint2*)&sW[((0 * 8 + ks) * 8 + nt) * 64 + lane * 2];
                const uint2 bn = *(const uint2*)&sW[((1 * 8 + ks) * 8 + nt) * 64 + lane * 2];

                asm volatile(
                    "mma.sync.aligned.m16n8k8.row.col.f32.tf32.tf32.f32 "
                    "{%0,%1,%2,%3}, {%4,%5,%6,%7}, {%8,%9}, {%0,%1,%2,%3};"
                    : "+f"(accX[q][0]), "+f"(accX[q][1]),
                      "+f"(accX[q][2]), "+f"(accX[q][3])
                    : "r"(a0), "r"(a1), "r"(a2), "r"(a3),
                      "r"(bx.x), "r"(bx.y));
                asm volatile(
                    "mma.sync.aligned.m16n8k8.row.col.f32.tf32.tf32.f32 "
                    "{%0,%1,%2,%3}, {%4,%5,%6,%7}, {%8,%9}, {%0,%1,%2,%3};"
                    : "+f"(accN[q][0]), "+f"(accN[q][1]),
                      "+f"(accN[q][2]), "+f"(accN[q][3])
                    : "r"(a0), "r"(a1), "r"(a2), "r"(a3),
                      "r"(bn.x), "r"(bn.y));
            }
        }

        #pragma unroll
        for (int q = 0; q < 4; ++q) {
            const int nt = h * 4 + q;
            const int c  = nt * 8 + 2 * t;
            const float2 bv = *(const float2*)&bias[c];
            if (r0 < NV) {
                *(float2*)&outb[(size_t)r0 * COUT + c] =
                    make_float2(accX[q][0] + bv.x, accX[q][1] + bv.y);
                *(float2*)&yb[(size_t)(r0 + 1) * COUT + c] =
                    make_float2(accN[q][0], accN[q][1]);
            }
            if (r1 < NV) {
                *(float2*)&outb[(size_t)r1 * COUT + c] =
                    make_float2(accX[q][2] + bv.x, accX[q][3] + bv.y);
                *(float2*)&yb[(size_t)(r1 + 1) * COUT + c] =
                    make_float2(accN[q][2], accN[q][3]);
            }
        }
    }
}

// ---------------------------------------------------------------------------
// Kernel B: out[b,v,:] += (1/K) * mean of y rows neighbor[v][k] (0 = pad row).
// Warp = 4 vertices. Per k-pair one LDG.128 covers 2 neighbor rows
// (lanes 0-15 -> even k, lanes 16-31 -> odd k). No guards, no branches.
// ---------------------------------------------------------------------------
__global__ __launch_bounds__(256)
void gather_add_kernel(const int* __restrict__ neighbor,
                       float*     __restrict__ out)
{
    __shared__ int sN[512];   // 32 verts * 16 ids

    const int tid  = threadIdx.x;
    const int warp = tid >> 5;
    const int lane = tid & 31;
    const int half = lane >> 4;          // 0 = even-k rows, 1 = odd-k rows
    const int l16  = lane & 15;
    const int vblk = blockIdx.x * 32;    // 625 * 32 = 20000 exactly
    const int v0   = vblk + warp * 4;
    const int b    = blockIdx.y;

    // Stage this CTA's 512 neighbor ids (one coalesced 2KB read).
    ((int2*)sN)[tid] = __ldg((const int2*)&neighbor[vblk * KNB] + tid);
    __syncthreads();

    const float* __restrict__ yb = g_y + (size_t)b * (NV + 1) * COUT;

    float4 acc0 = make_float4(0.f, 0.f, 0.f, 0.f);
    float4 acc1 = acc0, acc2 = acc0, acc3 = acc0;

    const int2* ids = (const int2*)&sN[warp * 4 * KNB];

    #pragma unroll
    for (int p = 0; p < 8; ++p) {
        const int2 i0 = ids[0 * 8 + p];          // uniform LDS.64 -> broadcast
        const int2 i1 = ids[1 * 8 + p];
        const int2 i2 = ids[2 * 8 + p];
        const int2 i3 = ids[3 * 8 + p];
        const int r0 = half ? i0.y : i0.x;       // id; 0 = zero pad row
        const int r1 = half ? i1.y : i1.x;
        const int r2 = half ? i2.y : i2.x;
        const int r3 = half ? i3.y : i3.x;

        const float4 t0 = *(const float4*)(yb + (size_t)r0 * COUT + l16 * 4);
        const float4 t1 = *(const float4*)(yb + (size_t)r1 * COUT + l16 * 4);
        const float4 t2 = *(const float4*)(yb + (size_t)r2 * COUT + l16 * 4);
        const float4 t3 = *(const float4*)(yb + (size_t)r3 * COUT + l16 * 4);

        acc0.x += t0.x; acc0.y += t0.y; acc0.z += t0.z; acc0.w += t0.w;
        acc1.x += t1.x; acc1.y += t1.y; acc1.z += t1.z; acc1.w += t1.w;
        acc2.x += t2.x; acc2.y += t2.y; acc2.z += t2.z; acc2.w += t2.w;
        acc3.x += t3.x; acc3.y += t3.y; acc3.z += t3.z; acc3.w += t3.w;
    }

    // Combine even/odd halves: butterfly across lane 16.
    #pragma unroll
    for (int c = 0; c < 4; ++c) {
        ((float*)&acc0)[c] += __shfl_xor_sync(0xffffffffu, ((float*)&acc0)[c], 16);
        ((float*)&acc1)[c] += __shfl_xor_sync(0xffffffffu, ((float*)&acc1)[c], 16);
        ((float*)&acc2)[c] += __shfl_xor_sync(0xffffffffu, ((float*)&acc2)[c], 16);
        ((float*)&acc3)[c] += __shfl_xor_sync(0xffffffffu, ((float*)&acc3)[c], 16);
    }

    // Pairwise RMW: low half -> vertex v0+0 / v0+2, high half -> v0+1 / v0+3.
    const float s = 1.0f / (float)KNB;
    const float4 sAB = half ? acc1 : acc0;
    const float4 sCD = half ? acc3 : acc2;

    float* opAB = out + ((size_t)b * NV + v0 + half)     * COUT + l16 * 4;
    float* opCD = out + ((size_t)b * NV + v0 + 2 + half) * COUT + l16 * 4;

    float4 oAB = *(const float4*)opAB;
    float4 oCD = *(const float4*)opCD;
    oAB.x += sAB.x * s; oAB.y += sAB.y * s; oAB.z += sAB.z * s; oAB.w += sAB.w * s;
    oCD.x += sCD.x * s; oCD.y += sCD.y * s; oCD.z += sCD.z * s; oCD.w += sCD.w * s;
    *(float4*)opAB = oAB;
    *(float4*)opCD = oCD;
}

extern "C" void kernel_launch(void* const* d_in, const int* in_sizes, int n_in,
                              void* d_out, int out_size)
{
    // metadata order: x, Wx, Wn, b, neighbor
    const float* x        = (const float*)d_in[0];
    const float* Wx       = (const float*)d_in[1];
    const float* Wn       = (const float*)d_in[2];
    const float* bias     = (const float*)d_in[3];
    const int*   neighbor = (const int*)d_in[4];
    float*       out      = (float*)d_out;

    wfrag_build_kernel<<<64, 256>>>(Wx, Wn);

    dim3 gridA((NV + 127) / 128, BATCH);        // 157 x 16
    gemm_tc_kernel<<<gridA, 256>>>(x, bias, out);

    dim3 gridB(NV / 32, BATCH);                 // 625 x 16
    gather_add_kernel<<<gridB, 256>>>(neighbor, out);
}

// round 15
// speedup vs baseline: 1.7504x; 1.0819x over previous
#include <cuda_runtime.h>
#include <cuda_fp16.h>
#include <cstdint>

#define BATCH 16
#define NV    20000
#define FIN   64
#define COUT  64
#define KNB   16

// Scratch: y = x @ Wn with a zero pad row at index 0.  [B][V+1][COUT]
__device__ float g_y[(size_t)BATCH * (NV + 1) * COUT];
// Weights as fp16 m16n8k16 B-fragments: [mat(2)][ks(4)][nt(8)][lane(32)] uint2
__device__ uint2 g_wfrag[2 * 4 * 8 * 32];

// ---------------------------------------------------------------------------
// Pre-kernel: pack Wx/Wn into m16n8k16 fp16 B-fragment order,
// and zero the pad rows of g_y (row 0 of each batch).
// Fragment (row.col): b0 = {W[k0+2t][n], W[k0+2t+1][n]}, b1 = +8 in k.
// ---------------------------------------------------------------------------
__global__ void wfrag_build_kernel(const float* __restrict__ Wx,
                                   const float* __restrict__ Wn)
{
    int i = blockIdx.x * 256 + threadIdx.x;        // 0..2047
    int lane =  i        & 31;
    int nt   = (i >> 5)  & 7;
    int ks   = (i >> 8)  & 3;
    int mat  =  i >> 10;
    int g = lane >> 2;
    int t = lane & 3;
    int k0 = 16 * ks;
    int n  = 8 * nt + g;
    const float* W = mat ? Wn : Wx;

    __half2 b0 = __floats2half2_rn(W[(k0 + 2 * t)     * COUT + n],
                                   W[(k0 + 2 * t + 1) * COUT + n]);
    __half2 b1 = __floats2half2_rn(W[(k0 + 2 * t + 8) * COUT + n],
                                   W[(k0 + 2 * t + 9) * COUT + n]);
    uint2 pk;
    pk.x = *(const uint32_t*)&b0;
    pk.y = *(const uint32_t*)&b1;
    g_wfrag[i] = pk;

    // Zero pad rows: 16 batches * 64 channels = 1024 floats
    if (i < BATCH * COUT) {
        int b = i >> 6;
        int c = i & 63;
        g_y[(size_t)b * (NV + 1) * COUT + c] = 0.f;
    }
}

// ---------------------------------------------------------------------------
// Kernel A: fp16 tensor-core dual GEMM (fp32 accum).
//   out = x@Wx + bias (d_out),  y = x@Wn (scratch, rows shifted +1)
// CTA = 128 verts, 8 warps; warp = 16 verts x 64 cols, K=64 (4 k-steps).
// ---------------------------------------------------------------------------
__global__ __launch_bounds__(256, 2)
void gemm_tc_kernel(const float* __restrict__ x,
                    const float* __restrict__ bias,
                    float*       __restrict__ out)
{
    __shared__ uint2 sW[2 * 4 * 8 * 32];           // 16 KB

    const int tid = threadIdx.x;

    // Stage fragment-ordered weights: 1024 uint4, 4 per thread, coalesced.
    {
        const uint4* src = (const uint4*)g_wfrag;
        uint4*       dst = (uint4*)sW;
        #pragma unroll
        for (int i = 0; i < 4; ++i)
            dst[tid + i * 256] = src[tid + i * 256];
    }
    __syncthreads();

    const int lane = tid & 31;
    const int wid  = tid >> 5;
    const int g    = lane >> 2;      // group id (row within m-tile)
    const int t    = lane & 3;       // thread-in-group
    const int b    = blockIdx.y;
    const int vb   = blockIdx.x * 128 + wid * 16;
    const int r0   = vb + g;
    const int r1   = r0 + 8;

    const float* __restrict__ xb = x + (size_t)b * NV * FIN;

    // ---- Prefetch A and convert to fp16 fragments --------------------------
    // Per k-step ks: a0 = row r0, cols (16ks+2t, +1); a2 = +8 in k; a1/a3 = r1.
    uint32_t ar0[4][2], ar1[4][2];
    #pragma unroll
    for (int ks = 0; ks < 4; ++ks) {
        #pragma unroll
        for (int m = 0; m < 2; ++m) {
            const int c = 16 * ks + 2 * t + 8 * m;
            float2 f0 = (r0 < NV) ? *(const float2*)&xb[(size_t)r0 * FIN + c]
                                  : make_float2(0.f, 0.f);
            float2 f1 = (r1 < NV) ? *(const float2*)&xb[(size_t)r1 * FIN + c]
                                  : make_float2(0.f, 0.f);
            __half2 h0 = __floats2half2_rn(f0.x, f0.y);
            __half2 h1 = __floats2half2_rn(f1.x, f1.y);
            ar0[ks][m] = *(const uint32_t*)&h0;
            ar1[ks][m] = *(const uint32_t*)&h1;
        }
    }

    // ---- Mainloop: 4 k-steps x 8 n-tiles x 2 matrices ----------------------
    float accX[8][4] = {{0.f}};
    float accN[8][4] = {{0.f}};

    #pragma unroll
    for (int ks = 0; ks < 4; ++ks) {
        const uint32_t a0 = ar0[ks][0];   // row g,   k 2t..2t+1
        const uint32_t a1 = ar1[ks][0];   // row g+8
        const uint32_t a2 = ar0[ks][1];   // row g,   k 2t+8..2t+9
        const uint32_t a3 = ar1[ks][1];   // row g+8

        #pragma unroll
        for (int nt = 0; nt < 8; ++nt) {
            const uint2 bx = sW[((0 * 4 + ks) * 8 + nt) * 32 + lane];
            const uint2 bn = sW[((1 * 4 + ks) * 8 + nt) * 32 + lane];

            asm volatile(
                "mma.sync.aligned.m16n8k16.row.col.f32.f16.f16.f32 "
                "{%0,%1,%2,%3}, {%4,%5,%6,%7}, {%8,%9}, {%0,%1,%2,%3};"
                : "+f"(accX[nt][0]), "+f"(accX[nt][1]),
                  "+f"(accX[nt][2]), "+f"(accX[nt][3])
                : "r"(a0), "r"(a1), "r"(a2), "r"(a3),
                  "r"(bx.x), "r"(bx.y));
            asm volatile(
                "mma.sync.aligned.m16n8k16.row.col.f32.f16.f16.f32 "
                "{%0,%1,%2,%3}, {%4,%5,%6,%7}, {%8,%9}, {%0,%1,%2,%3};"
                : "+f"(accN[nt][0]), "+f"(accN[nt][1]),
                  "+f"(accN[nt][2]), "+f"(accN[nt][3])
                : "r"(a0), "r"(a1), "r"(a2), "r"(a3),
                  "r"(bn.x), "r"(bn.y));
        }
    }

    // ---- Epilogue: out rows; y rows shifted +1 (row 0 = zero pad) ----------
    float* __restrict__ outb = out + (size_t)b * NV * COUT;
    float* __restrict__ yb   = g_y + (size_t)b * (NV + 1) * COUT;
    #pragma unroll
    for (int nt = 0; nt < 8; ++nt) {
        const int c = nt * 8 + 2 * t;
        const float2 bv = *(const float2*)&bias[c];
        if (r0 < NV) {
            *(float2*)&outb[(size_t)r0 * COUT + c] =
                make_float2(accX[nt][0] + bv.x, accX[nt][1] + bv.y);
            *(float2*)&yb[(size_t)(r0 + 1) * COUT + c] =
                make_float2(accN[nt][0], accN[nt][1]);
        }
        if (r1 < NV) {
            *(float2*)&outb[(size_t)r1 * COUT + c] =
                make_float2(accX[nt][2] + bv.x, accX[nt][3] + bv.y);
            *(float2*)&yb[(size_t)(r1 + 1) * COUT + c] =
                make_float2(accN[nt][2], accN[nt][3]);
        }
    }
}

// ---------------------------------------------------------------------------
// Kernel B: out[b,v,:] += (1/K) * mean of y rows neighbor[v][k] (0 = pad row).
// Warp = 4 vertices. Per k-pair one LDG.128 covers 2 neighbor rows
// (lanes 0-15 -> even k, lanes 16-31 -> odd k). No guards, no branches.
// ---------------------------------------------------------------------------
__global__ __launch_bounds__(256)
void gather_add_kernel(const int* __restrict__ neighbor,
                       float*     __restrict__ out)
{
    __shared__ int sN[512];   // 32 verts * 16 ids

    const int tid  = threadIdx.x;
    const int warp = tid >> 5;
    const int lane = tid & 31;
    const int half = lane >> 4;          // 0 = even-k rows, 1 = odd-k rows
    const int l16  = lane & 15;
    const int vblk = blockIdx.x * 32;    // 625 * 32 = 20000 exactly
    const int v0   = vblk + warp * 4;
    const int b    = blockIdx.y;

    // Stage this CTA's 512 neighbor ids (one coalesced 2KB read).
    ((int2*)sN)[tid] = __ldg((const int2*)&neighbor[vblk * KNB] + tid);
    __syncthreads();

    const float* __restrict__ yb = g_y + (size_t)b * (NV + 1) * COUT;

    float4 acc0 = make_float4(0.f, 0.f, 0.f, 0.f);
    float4 acc1 = acc0, acc2 = acc0, acc3 = acc0;

    const int2* ids = (const int2*)&sN[warp * 4 * KNB];

    #pragma unroll
    for (int p = 0; p < 8; ++p) {
        const int2 i0 = ids[0 * 8 + p];          // uniform LDS.64 -> broadcast
        const int2 i1 = ids[1 * 8 + p];
        const int2 i2 = ids[2 * 8 + p];
        const int2 i3 = ids[3 * 8 + p];
        const int r0 = half ? i0.y : i0.x;       // id; 0 = zero pad row
        const int r1 = half ? i1.y : i1.x;
        const int r2 = half ? i2.y : i2.x;
        const int r3 = half ? i3.y : i3.x;

        const float4 t0 = *(const float4*)(yb + (size_t)r0 * COUT + l16 * 4);
        const float4 t1 = *(const float4*)(yb + (size_t)r1 * COUT + l16 * 4);
        const float4 t2 = *(const float4*)(yb + (size_t)r2 * COUT + l16 * 4);
        const float4 t3 = *(const float4*)(yb + (size_t)r3 * COUT + l16 * 4);

        acc0.x += t0.x; acc0.y += t0.y; acc0.z += t0.z; acc0.w += t0.w;
        acc1.x += t1.x; acc1.y += t1.y; acc1.z += t1.z; acc1.w += t1.w;
        acc2.x += t2.x; acc2.y += t2.y; acc2.z += t2.z; acc2.w += t2.w;
        acc3.x += t3.x; acc3.y += t3.y; acc3.z += t3.z; acc3.w += t3.w;
    }

    // Combine even/odd halves: butterfly across lane 16.
    #pragma unroll
    for (int c = 0; c < 4; ++c) {
        ((float*)&acc0)[c] += __shfl_xor_sync(0xffffffffu, ((float*)&acc0)[c], 16);
        ((float*)&acc1)[c] += __shfl_xor_sync(0xffffffffu, ((float*)&acc1)[c], 16);
        ((float*)&acc2)[c] += __shfl_xor_sync(0xffffffffu, ((float*)&acc2)[c], 16);
        ((float*)&acc3)[c] += __shfl_xor_sync(0xffffffffu, ((float*)&acc3)[c], 16);
    }

    // Pairwise RMW: low half -> vertex v0+0 / v0+2, high half -> v0+1 / v0+3.
    const float s = 1.0f / (float)KNB;
    const float4 sAB = half ? acc1 : acc0;
    const float4 sCD = half ? acc3 : acc2;

    float* opAB = out + ((size_t)b * NV + v0 + half)     * COUT + l16 * 4;
    float* opCD = out + ((size_t)b * NV + v0 + 2 + half) * COUT + l16 * 4;

    float4 oAB = *(const float4*)opAB;
    float4 oCD = *(const float4*)opCD;
    oAB.x += sAB.x * s; oAB.y += sAB.y * s; oAB.z += sAB.z * s; oAB.w += sAB.w * s;
    oCD.x += sCD.x * s; oCD.y += sCD.y * s; oCD.z += sCD.z * s; oCD.w += sCD.w * s;
    *(float4*)opAB = oAB;
    *(float4*)opCD = oCD;
}

extern "C" void kernel_launch(void* const* d_in, const int* in_sizes, int n_in,
                              void* d_out, int out_size)
{
    // metadata order: x, Wx, Wn, b, neighbor
    const float* x        = (const float*)d_in[0];
    const float* Wx       = (const float*)d_in[1];
    const float* Wn       = (const float*)d_in[2];
    const float* bias     = (const float*)d_in[3];
    const int*   neighbor = (const int*)d_in[4];
    float*       out      = (float*)d_out;

    wfrag_build_kernel<<<8, 256>>>(Wx, Wn);

    dim3 gridA((NV + 127) / 128, BATCH);        // 157 x 16
    gemm_tc_kernel<<<gridA, 256>>>(x, bias, out);

    dim3 gridB(NV / 32, BATCH);                 // 625 x 16
    gather_add_kernel<<<gridB, 256>>>(neighbor, out);
}

// round 16
// speedup vs baseline: 2.1067x; 1.2036x over previous
#include <cuda_runtime.h>
#include <cuda_fp16.h>
#include <cstdint>

#define BATCH 16
#define NV    20000
#define FIN   64
#define COUT  64
#define KNB   16

// Scratch: y = x @ Wn in fp16 (packed half2), zero pad row at index 0.
// [B][V+1][COUT/2] uint32; row = 128 B.
__device__ uint32_t g_y[(size_t)BATCH * (NV + 1) * (COUT / 2)];
// Weights as fp16 m16n8k16 B-fragments: [mat(2)][ks(4)][nt(8)][lane(32)] uint2
__device__ uint2 g_wfrag[2 * 4 * 8 * 32];

// ---------------------------------------------------------------------------
// Pre-kernel: pack Wx/Wn into m16n8k16 fp16 B-fragment order,
// and zero the fp16 pad rows of g_y (row 0 of each batch).
// ---------------------------------------------------------------------------
__global__ void wfrag_build_kernel(const float* __restrict__ Wx,
                                   const float* __restrict__ Wn)
{
    int i = blockIdx.x * 256 + threadIdx.x;        // 0..2047
    int lane =  i        & 31;
    int nt   = (i >> 5)  & 7;
    int ks   = (i >> 8)  & 3;
    int mat  =  i >> 10;
    int g = lane >> 2;
    int t = lane & 3;
    int k0 = 16 * ks;
    int n  = 8 * nt + g;
    const float* W = mat ? Wn : Wx;

    __half2 b0 = __floats2half2_rn(W[(k0 + 2 * t)     * COUT + n],
                                   W[(k0 + 2 * t + 1) * COUT + n]);
    __half2 b1 = __floats2half2_rn(W[(k0 + 2 * t + 8) * COUT + n],
                                   W[(k0 + 2 * t + 9) * COUT + n]);
    uint2 pk;
    pk.x = *(const uint32_t*)&b0;
    pk.y = *(const uint32_t*)&b1;
    g_wfrag[i] = pk;

    // Zero fp16 pad rows: 16 batches * 32 uint32
    if (i < BATCH * (COUT / 2)) {
        int b = i >> 5;
        int c = i & 31;
        g_y[(size_t)b * (NV + 1) * (COUT / 2) + c] = 0u;
    }
}

// ---------------------------------------------------------------------------
// Kernel A: fp16 tensor-core dual GEMM (fp32 accum).
//   out = x@Wx + bias (d_out),  y = x@Wn (fp16 scratch, rows shifted +1)
// CTA = 128 verts, 8 warps; warp = 16 verts x 64 cols, K=64 (4 k-steps).
// ---------------------------------------------------------------------------
__global__ __launch_bounds__(256, 2)
void gemm_tc_kernel(const float* __restrict__ x,
                    const float* __restrict__ bias,
                    float*       __restrict__ out)
{
    __shared__ uint2 sW[2 * 4 * 8 * 32];           // 16 KB

    const int tid = threadIdx.x;

    // Stage fragment-ordered weights: 1024 uint4, 4 per thread, coalesced.
    {
        const uint4* src = (const uint4*)g_wfrag;
        uint4*       dst = (uint4*)sW;
        #pragma unroll
        for (int i = 0; i < 4; ++i)
            dst[tid + i * 256] = src[tid + i * 256];
    }
    __syncthreads();

    const int lane = tid & 31;
    const int wid  = tid >> 5;
    const int g    = lane >> 2;      // group id (row within m-tile)
    const int t    = lane & 3;       // thread-in-group
    const int b    = blockIdx.y;
    const int vb   = blockIdx.x * 128 + wid * 16;
    const int r0   = vb + g;
    const int r1   = r0 + 8;

    const float* __restrict__ xb = x + (size_t)b * NV * FIN;

    // ---- Prefetch A and convert to fp16 fragments --------------------------
    uint32_t ar0[4][2], ar1[4][2];
    #pragma unroll
    for (int ks = 0; ks < 4; ++ks) {
        #pragma unroll
        for (int m = 0; m < 2; ++m) {
            const int c = 16 * ks + 2 * t + 8 * m;
            float2 f0 = (r0 < NV) ? *(const float2*)&xb[(size_t)r0 * FIN + c]
                                  : make_float2(0.f, 0.f);
            float2 f1 = (r1 < NV) ? *(const float2*)&xb[(size_t)r1 * FIN + c]
                                  : make_float2(0.f, 0.f);
            __half2 h0 = __floats2half2_rn(f0.x, f0.y);
            __half2 h1 = __floats2half2_rn(f1.x, f1.y);
            ar0[ks][m] = *(const uint32_t*)&h0;
            ar1[ks][m] = *(const uint32_t*)&h1;
        }
    }

    // ---- Mainloop: 4 k-steps x 8 n-tiles x 2 matrices ----------------------
    float accX[8][4] = {{0.f}};
    float accN[8][4] = {{0.f}};

    #pragma unroll
    for (int ks = 0; ks < 4; ++ks) {
        const uint32_t a0 = ar0[ks][0];
        const uint32_t a1 = ar1[ks][0];
        const uint32_t a2 = ar0[ks][1];
        const uint32_t a3 = ar1[ks][1];

        #pragma unroll
        for (int nt = 0; nt < 8; ++nt) {
            const uint2 bx = sW[((0 * 4 + ks) * 8 + nt) * 32 + lane];
            const uint2 bn = sW[((1 * 4 + ks) * 8 + nt) * 32 + lane];

            asm volatile(
                "mma.sync.aligned.m16n8k16.row.col.f32.f16.f16.f32 "
                "{%0,%1,%2,%3}, {%4,%5,%6,%7}, {%8,%9}, {%0,%1,%2,%3};"
                : "+f"(accX[nt][0]), "+f"(accX[nt][1]),
                  "+f"(accX[nt][2]), "+f"(accX[nt][3])
                : "r"(a0), "r"(a1), "r"(a2), "r"(a3),
                  "r"(bx.x), "r"(bx.y));
            asm volatile(
                "mma.sync.aligned.m16n8k16.row.col.f32.f16.f16.f32 "
                "{%0,%1,%2,%3}, {%4,%5,%6,%7}, {%8,%9}, {%0,%1,%2,%3};"
                : "+f"(accN[nt][0]), "+f"(accN[nt][1]),
                  "+f"(accN[nt][2]), "+f"(accN[nt][3])
                : "r"(a0), "r"(a1), "r"(a2), "r"(a3),
                  "r"(bn.x), "r"(bn.y));
        }
    }

    // ---- Epilogue: out fp32; y packed fp16 (rows shifted +1) ---------------
    float*    __restrict__ outb = out + (size_t)b * NV * COUT;
    uint32_t* __restrict__ yb   = g_y + (size_t)b * (NV + 1) * (COUT / 2);
    #pragma unroll
    for (int nt = 0; nt < 8; ++nt) {
        const int c  = nt * 8 + 2 * t;
        const int ch = nt * 4 + t;        // packed half2 index c/2
        const float2 bv = *(const float2*)&bias[c];
        if (r0 < NV) {
            *(float2*)&outb[(size_t)r0 * COUT + c] =
                make_float2(accX[nt][0] + bv.x, accX[nt][1] + bv.y);
            __half2 p = __floats2half2_rn(accN[nt][0], accN[nt][1]);
            yb[(size_t)(r0 + 1) * (COUT / 2) + ch] = *(const uint32_t*)&p;
        }
        if (r1 < NV) {
            *(float2*)&outb[(size_t)r1 * COUT + c] =
                make_float2(accX[nt][2] + bv.x, accX[nt][3] + bv.y);
            __half2 p = __floats2half2_rn(accN[nt][2], accN[nt][3]);
            yb[(size_t)(r1 + 1) * (COUT / 2) + ch] = *(const uint32_t*)&p;
        }
    }
}

// ---------------------------------------------------------------------------
// Kernel B: out[b,v,:] += (1/K) * mean of fp16 y rows (0 = pad row).
// Warp = 4 vertices. Per k-pair one LDG.64 covers 2 neighbor rows
// (lanes 0-15 -> even k, lanes 16-31 -> odd k). HADD2 accumulation,
// no unpack, no guards, no branches.
// ---------------------------------------------------------------------------
__global__ __launch_bounds__(256)
void gather_add_kernel(const int* __restrict__ neighbor,
                       float*     __restrict__ out)
{
    __shared__ int sN[512];   // 32 verts * 16 ids

    const int tid  = threadIdx.x;
    const int warp = tid >> 5;
    const int lane = tid & 31;
    const int half = lane >> 4;          // 0 = even-k rows, 1 = odd-k rows
    const int l16  = lane & 15;
    const int vblk = blockIdx.x * 32;    // 625 * 32 = 20000 exactly
    const int v0   = vblk + warp * 4;
    const int b    = blockIdx.y;

    // Stage this CTA's 512 neighbor ids (one coalesced 2KB read).
    ((int2*)sN)[tid] = __ldg((const int2*)&neighbor[vblk * KNB] + tid);
    __syncthreads();

    // fp16 y rows: 32 uint32 each = 16 uint2; lane covers channels l16*4..+3
    const uint2* __restrict__ yb =
        (const uint2*)(g_y + (size_t)b * (NV + 1) * (COUT / 2));

    __half2 aL0 = __float2half2_rn(0.f), aH0 = aL0;
    __half2 aL1 = aL0, aH1 = aL0;
    __half2 aL2 = aL0, aH2 = aL0;
    __half2 aL3 = aL0, aH3 = aL0;

    const int2* ids = (const int2*)&sN[warp * 4 * KNB];

    #pragma unroll
    for (int p = 0; p < 8; ++p) {
        const int2 i0 = ids[0 * 8 + p];          // uniform LDS.64 -> broadcast
        const int2 i1 = ids[1 * 8 + p];
        const int2 i2 = ids[2 * 8 + p];
        const int2 i3 = ids[3 * 8 + p];
        const int r0 = half ? i0.y : i0.x;       // id; 0 = zero pad row
        const int r1 = half ? i1.y : i1.x;
        const int r2 = half ? i2.y : i2.x;
        const int r3 = half ? i3.y : i3.x;

        const uint2 t0 = yb[(size_t)r0 * 16 + l16];
        const uint2 t1 = yb[(size_t)r1 * 16 + l16];
        const uint2 t2 = yb[(size_t)r2 * 16 + l16];
        const uint2 t3 = yb[(size_t)r3 * 16 + l16];

        aL0 = __hadd2(aL0, *(const __half2*)&t0.x);
        aH0 = __hadd2(aH0, *(const __half2*)&t0.y);
        aL1 = __hadd2(aL1, *(const __half2*)&t1.x);
        aH1 = __hadd2(aH1, *(const __half2*)&t1.y);
        aL2 = __hadd2(aL2, *(const __half2*)&t2.x);
        aH2 = __hadd2(aH2, *(const __half2*)&t2.y);
        aL3 = __hadd2(aL3, *(const __half2*)&t3.x);
        aH3 = __hadd2(aH3, *(const __half2*)&t3.y);
    }

    // Combine even/odd halves: butterfly across lane 16 (uint32 shuffle).
    #pragma unroll
    for (int q = 0; q < 1; ++q) { }   // (structure kept flat below)
    {
        uint32_t u;
        u = __shfl_xor_sync(0xffffffffu, *(const uint32_t*)&aL0, 16);
        aL0 = __hadd2(aL0, *(const __half2*)&u);
        u = __shfl_xor_sync(0xffffffffu, *(const uint32_t*)&aH0, 16);
        aH0 = __hadd2(aH0, *(const __half2*)&u);
        u = __shfl_xor_sync(0xffffffffu, *(const uint32_t*)&aL1, 16);
        aL1 = __hadd2(aL1, *(const __half2*)&u);
        u = __shfl_xor_sync(0xffffffffu, *(const uint32_t*)&aH1, 16);
        aH1 = __hadd2(aH1, *(const __half2*)&u);
        u = __shfl_xor_sync(0xffffffffu, *(const uint32_t*)&aL2, 16);
        aL2 = __hadd2(aL2, *(const __half2*)&u);
        u = __shfl_xor_sync(0xffffffffu, *(const uint32_t*)&aH2, 16);
        aH2 = __hadd2(aH2, *(const __half2*)&u);
        u = __shfl_xor_sync(0xffffffffu, *(const uint32_t*)&aL3, 16);
        aL3 = __hadd2(aL3, *(const __half2*)&u);
        u = __shfl_xor_sync(0xffffffffu, *(const uint32_t*)&aH3, 16);
        aH3 = __hadd2(aH3, *(const __half2*)&u);
    }

    // Pairwise RMW: low half -> vertex v0+0 / v0+2, high half -> v0+1 / v0+3.
    const float s = 1.0f / (float)KNB;
    const __half2 sabL = half ? aL1 : aL0;
    const __half2 sabH = half ? aH1 : aH0;
    const __half2 scdL = half ? aL3 : aL2;
    const __half2 scdH = half ? aH3 : aH2;

    const float2 abL = __half22float2(sabL);
    const float2 abH = __half22float2(sabH);
    const float2 cdL = __half22float2(scdL);
    const float2 cdH = __half22float2(scdH);

    float* opAB = out + ((size_t)b * NV + v0 + half)     * COUT + l16 * 4;
    float* opCD = out + ((size_t)b * NV + v0 + 2 + half) * COUT + l16 * 4;

    float4 oAB = *(const float4*)opAB;
    float4 oCD = *(const float4*)opCD;
    oAB.x += abL.x * s; oAB.y += abL.y * s; oAB.z += abH.x * s; oAB.w += abH.y * s;
    oCD.x += cdL.x * s; oCD.y += cdL.y * s; oCD.z += cdH.x * s; oCD.w += cdH.y * s;
    *(float4*)opAB = oAB;
    *(float4*)opCD = oCD;
}

extern "C" void kernel_launch(void* const* d_in, const int* in_sizes, int n_in,
                              void* d_out, int out_size)
{
    // metadata order: x, Wx, Wn, b, neighbor
    const float* x        = (const float*)d_in[0];
    const float* Wx       = (const float*)d_in[1];
    const float* Wn       = (const float*)d_in[2];
    const float* bias     = (const float*)d_in[3];
    const int*   neighbor = (const int*)d_in[4];
    float*       out      = (float*)d_out;

    wfrag_build_kernel<<<8, 256>>>(Wx, Wn);

    dim3 gridA((NV + 127) / 128, BATCH);        // 157 x 16
    gemm_tc_kernel<<<gridA, 256>>>(x, bias, out);

    dim3 gridB(NV / 32, BATCH);                 // 625 x 16
    gather_add_kernel<<<gridB, 256>>>(neighbor, out);
}

// round 17
// speedup vs baseline: 2.2902x; 1.0871x over previous
#include <cuda_runtime.h>
#include <cuda_fp16.h>
#include <cstdint>

#define BATCH 16
#define NV    20000
#define FIN   64
#define COUT  64
#define KNB   16

#define BLKS_PER_B 157                 // ceil(20000/128)
#define NTILES     (BLKS_PER_B * BATCH)  // 2512
#define GRID_A     296                 // 2 CTAs/SM x 148: fully persistent

// Scratch: y = x @ Wn in fp16 (packed half2), zero pad row at index 0.
// [B][V+1][COUT/2] uint32; row = 128 B.
__device__ uint32_t g_y[(size_t)BATCH * (NV + 1) * (COUT / 2)];
// Weights as fp16 m16n8k16 B-fragments: [mat(2)][ks(4)][nt(8)][lane(32)] uint2
__device__ uint2 g_wfrag[2 * 4 * 8 * 32];

// ---------------------------------------------------------------------------
// Pre-kernel: pack Wx/Wn into m16n8k16 fp16 B-fragment order,
// and zero the fp16 pad rows of g_y (row 0 of each batch).
// ---------------------------------------------------------------------------
__global__ void wfrag_build_kernel(const float* __restrict__ Wx,
                                   const float* __restrict__ Wn)
{
    int i = blockIdx.x * 256 + threadIdx.x;        // 0..2047
    int lane =  i        & 31;
    int nt   = (i >> 5)  & 7;
    int ks   = (i >> 8)  & 3;
    int mat  =  i >> 10;
    int g = lane >> 2;
    int t = lane & 3;
    int k0 = 16 * ks;
    int n  = 8 * nt + g;
    const float* W = mat ? Wn : Wx;

    __half2 b0 = __floats2half2_rn(W[(k0 + 2 * t)     * COUT + n],
                                   W[(k0 + 2 * t + 1) * COUT + n]);
    __half2 b1 = __floats2half2_rn(W[(k0 + 2 * t + 8) * COUT + n],
                                   W[(k0 + 2 * t + 9) * COUT + n]);
    uint2 pk;
    pk.x = *(const uint32_t*)&b0;
    pk.y = *(const uint32_t*)&b1;
    g_wfrag[i] = pk;

    // Zero fp16 pad rows: 16 batches * 32 uint32
    if (i < BATCH * (COUT / 2)) {
        int b = i >> 5;
        int c = i & 31;
        g_y[(size_t)b * (NV + 1) * (COUT / 2) + c] = 0u;
    }
}

// ---------------------------------------------------------------------------
// A-tile prefetch: 16 independent LDG.64 per thread (2 rows x 8 col-pairs).
// ---------------------------------------------------------------------------
__device__ __forceinline__ void prefetch_a(const float* __restrict__ x,
                                           int tl, int wid, int g, int t,
                                           float2* F0, float2* F1)
{
    const int b   = tl / BLKS_PER_B;
    const int blk = tl - b * BLKS_PER_B;
    const int vb  = blk * 128 + wid * 16;
    const int r0  = vb + g;
    const int r1  = r0 + 8;
    const float* __restrict__ xb = x + (size_t)b * NV * FIN;
    #pragma unroll
    for (int j = 0; j < 8; ++j) {
        const int ks = j >> 1, m = j & 1;
        const int c  = 16 * ks + 2 * t + 8 * m;
        F0[j] = (r0 < NV) ? *(const float2*)&xb[(size_t)r0 * FIN + c]
                          : make_float2(0.f, 0.f);
        F1[j] = (r1 < NV) ? *(const float2*)&xb[(size_t)r1 * FIN + c]
                          : make_float2(0.f, 0.f);
    }
}

// ---------------------------------------------------------------------------
// Kernel A: PERSISTENT fp16 tensor-core dual GEMM (fp32 accum).
//   out = x@Wx + bias (d_out),  y = x@Wn (fp16 scratch, rows shifted +1)
// 296 resident CTAs; each loops ~8.5 tiles. Weights staged ONCE per CTA;
// tile i+1's A-loads are issued before tile i's mainloop (latency hidden).
// ---------------------------------------------------------------------------
__global__ __launch_bounds__(256, 2)
void gemm_tc_kernel(const float* __restrict__ x,
                    const float* __restrict__ bias,
                    float*       __restrict__ out)
{
    __shared__ uint2 sW[2 * 4 * 8 * 32];           // 16 KB

    const int tid = threadIdx.x;

    // Stage fragment-ordered weights ONCE: 1024 uint4, coalesced.
    {
        const uint4* src = (const uint4*)g_wfrag;
        uint4*       dst = (uint4*)sW;
        #pragma unroll
        for (int i = 0; i < 4; ++i)
            dst[tid + i * 256] = src[tid + i * 256];
    }
    __syncthreads();

    const int lane = tid & 31;
    const int wid  = tid >> 5;
    const int g    = lane >> 2;
    const int t    = lane & 3;

    int tile = blockIdx.x;
    if (tile >= NTILES) return;

    float2 F0[8], F1[8];                 // fp32 prefetch buffers
    prefetch_a(x, tile, wid, g, t, F0, F1);

    while (tile < NTILES) {
        const int b   = tile / BLKS_PER_B;
        const int blk = tile - b * BLKS_PER_B;
        const int vb  = blk * 128 + wid * 16;
        const int r0  = vb + g;
        const int r1  = r0 + 8;

        // Convert current tile's A to fp16 fragments (frees F for next tile).
        uint32_t ar0[8], ar1[8];         // index j = ks*2 + m
        #pragma unroll
        for (int j = 0; j < 8; ++j) {
            __half2 h0 = __floats2half2_rn(F0[j].x, F0[j].y);
            __half2 h1 = __floats2half2_rn(F1[j].x, F1[j].y);
            ar0[j] = *(const uint32_t*)&h0;
            ar1[j] = *(const uint32_t*)&h1;
        }

        // Issue next tile's loads NOW; they complete under the mainloop.
        const int next = tile + GRID_A;
        if (next < NTILES)
            prefetch_a(x, next, wid, g, t, F0, F1);

        float*    __restrict__ outb = out + (size_t)b * NV * COUT;
        uint32_t* __restrict__ yb   = g_y + (size_t)b * (NV + 1) * (COUT / 2);

        // Mainloop + epilogue in two nt-halves (32 live acc regs).
        #pragma unroll
        for (int h = 0; h < 2; ++h) {
            float accX[4][4] = {{0.f}};
            float accN[4][4] = {{0.f}};

            #pragma unroll
            for (int ks = 0; ks < 4; ++ks) {
                const uint32_t a0 = ar0[2 * ks];
                const uint32_t a1 = ar1[2 * ks];
                const uint32_t a2 = ar0[2 * ks + 1];
                const uint32_t a3 = ar1[2 * ks + 1];

                #pragma unroll
                for (int q = 0; q < 4; ++q) {
                    const int nt = h * 4 + q;
                    const uint2 bx = sW[((0 * 4 + ks) * 8 + nt) * 32 + lane];
                    const uint2 bn = sW[((1 * 4 + ks) * 8 + nt) * 32 + lane];

                    asm volatile(
                        "mma.sync.aligned.m16n8k16.row.col.f32.f16.f16.f32 "
                        "{%0,%1,%2,%3}, {%4,%5,%6,%7}, {%8,%9}, {%0,%1,%2,%3};"
                        : "+f"(accX[q][0]), "+f"(accX[q][1]),
                          "+f"(accX[q][2]), "+f"(accX[q][3])
                        : "r"(a0), "r"(a1), "r"(a2), "r"(a3),
                          "r"(bx.x), "r"(bx.y));
                    asm volatile(
                        "mma.sync.aligned.m16n8k16.row.col.f32.f16.f16.f32 "
                        "{%0,%1,%2,%3}, {%4,%5,%6,%7}, {%8,%9}, {%0,%1,%2,%3};"
                        : "+f"(accN[q][0]), "+f"(accN[q][1]),
                          "+f"(accN[q][2]), "+f"(accN[q][3])
                        : "r"(a0), "r"(a1), "r"(a2), "r"(a3),
                          "r"(bn.x), "r"(bn.y));
                }
            }

            #pragma unroll
            for (int q = 0; q < 4; ++q) {
                const int nt = h * 4 + q;
                const int c  = nt * 8 + 2 * t;
                const int ch = nt * 4 + t;
                const float2 bv = *(const float2*)&bias[c];
                if (r0 < NV) {
                    *(float2*)&outb[(size_t)r0 * COUT + c] =
                        make_float2(accX[q][0] + bv.x, accX[q][1] + bv.y);
                    __half2 p = __floats2half2_rn(accN[q][0], accN[q][1]);
                    yb[(size_t)(r0 + 1) * (COUT / 2) + ch] = *(const uint32_t*)&p;
                }
                if (r1 < NV) {
                    *(float2*)&outb[(size_t)r1 * COUT + c] =
                        make_float2(accX[q][2] + bv.x, accX[q][3] + bv.y);
                    __half2 p = __floats2half2_rn(accN[q][2], accN[q][3]);
                    yb[(size_t)(r1 + 1) * (COUT / 2) + ch] = *(const uint32_t*)&p;
                }
            }
        }

        tile = next;
    }
}

// ---------------------------------------------------------------------------
// Kernel B: out[b,v,:] += (1/K) * mean of fp16 y rows (0 = pad row).
// Warp = 4 vertices. Per k-pair one LDG.64 covers 2 neighbor rows
// (lanes 0-15 -> even k, lanes 16-31 -> odd k). HADD2 accumulation.
// ---------------------------------------------------------------------------
__global__ __launch_bounds__(256)
void gather_add_kernel(const int* __restrict__ neighbor,
                       float*     __restrict__ out)
{
    __shared__ int sN[512];   // 32 verts * 16 ids

    const int tid  = threadIdx.x;
    const int warp = tid >> 5;
    const int lane = tid & 31;
    const int half = lane >> 4;          // 0 = even-k rows, 1 = odd-k rows
    const int l16  = lane & 15;
    const int vblk = blockIdx.x * 32;    // 625 * 32 = 20000 exactly
    const int v0   = vblk + warp * 4;
    const int b    = blockIdx.y;

    // Stage this CTA's 512 neighbor ids (one coalesced 2KB read).
    ((int2*)sN)[tid] = __ldg((const int2*)&neighbor[vblk * KNB] + tid);
    __syncthreads();

    const uint2* __restrict__ yb =
        (const uint2*)(g_y + (size_t)b * (NV + 1) * (COUT / 2));

    __half2 aL0 = __float2half2_rn(0.f), aH0 = aL0;
    __half2 aL1 = aL0, aH1 = aL0;
    __half2 aL2 = aL0, aH2 = aL0;
    __half2 aL3 = aL0, aH3 = aL0;

    const int2* ids = (const int2*)&sN[warp * 4 * KNB];

    #pragma unroll
    for (int p = 0; p < 8; ++p) {
        const int2 i0 = ids[0 * 8 + p];          // uniform LDS.64 -> broadcast
        const int2 i1 = ids[1 * 8 + p];
        const int2 i2 = ids[2 * 8 + p];
        const int2 i3 = ids[3 * 8 + p];
        const int r0 = half ? i0.y : i0.x;       // id; 0 = zero pad row
        const int r1 = half ? i1.y : i1.x;
        const int r2 = half ? i2.y : i2.x;
        const int r3 = half ? i3.y : i3.x;

        const uint2 t0 = yb[(size_t)r0 * 16 + l16];
        const uint2 t1 = yb[(size_t)r1 * 16 + l16];
        const uint2 t2 = yb[(size_t)r2 * 16 + l16];
        const uint2 t3 = yb[(size_t)r3 * 16 + l16];

        aL0 = __hadd2(aL0, *(const __half2*)&t0.x);
        aH0 = __hadd2(aH0, *(const __half2*)&t0.y);
        aL1 = __hadd2(aL1, *(const __half2*)&t1.x);
        aH1 = __hadd2(aH1, *(const __half2*)&t1.y);
        aL2 = __hadd2(aL2, *(const __half2*)&t2.x);
        aH2 = __hadd2(aH2, *(const __half2*)&t2.y);
        aL3 = __hadd2(aL3, *(const __half2*)&t3.x);
        aH3 = __hadd2(aH3, *(const __half2*)&t3.y);
    }

    // Combine even/odd halves: butterfly across lane 16 (uint32 shuffle).
    {
        uint32_t u;
        u = __shfl_xor_sync(0xffffffffu, *(const uint32_t*)&aL0, 16);
        aL0 = __hadd2(aL0, *(const __half2*)&u);
        u = __shfl_xor_sync(0xffffffffu, *(const uint32_t*)&aH0, 16);
        aH0 = __hadd2(aH0, *(const __half2*)&u);
        u = __shfl_xor_sync(0xffffffffu, *(const uint32_t*)&aL1, 16);
        aL1 = __hadd2(aL1, *(const __half2*)&u);
        u = __shfl_xor_sync(0xffffffffu, *(const uint32_t*)&aH1, 16);
        aH1 = __hadd2(aH1, *(const __half2*)&u);
        u = __shfl_xor_sync(0xffffffffu, *(const uint32_t*)&aL2, 16);
        aL2 = __hadd2(aL2, *(const __half2*)&u);
        u = __shfl_xor_sync(0xffffffffu, *(const uint32_t*)&aH2, 16);
        aH2 = __hadd2(aH2, *(const __half2*)&u);
        u = __shfl_xor_sync(0xffffffffu, *(const uint32_t*)&aL3, 16);
        aL3 = __hadd2(aL3, *(const __half2*)&u);
        u = __shfl_xor_sync(0xffffffffu, *(const uint32_t*)&aH3, 16);
        aH3 = __hadd2(aH3, *(const __half2*)&u);
    }

    // Pairwise RMW: low half -> vertex v0+0 / v0+2, high half -> v0+1 / v0+3.
    const float s = 1.0f / (float)KNB;
    const __half2 sabL = half ? aL1 : aL0;
    const __half2 sabH = half ? aH1 : aH0;
    const __half2 scdL = half ? aL3 : aL2;
    const __half2 scdH = half ? aH3 : aH2;

    const float2 abL = __half22float2(sabL);
    const float2 abH = __half22float2(sabH);
    const float2 cdL = __half22float2(scdL);
    const float2 cdH = __half22float2(scdH);

    float* opAB = out + ((size_t)b * NV + v0 + half)     * COUT + l16 * 4;
    float* opCD = out + ((size_t)b * NV + v0 + 2 + half) * COUT + l16 * 4;

    float4 oAB = *(const float4*)opAB;
    float4 oCD = *(const float4*)opCD;
    oAB.x += abL.x * s; oAB.y += abL.y * s; oAB.z += abH.x * s; oAB.w += abH.y * s;
    oCD.x += cdL.x * s; oCD.y += cdL.y * s; oCD.z += cdH.x * s; oCD.w += cdH.y * s;
    *(float4*)opAB = oAB;
    *(float4*)opCD = oCD;
}

extern "C" void kernel_launch(void* const* d_in, const int* in_sizes, int n_in,
                              void* d_out, int out_size)
{
    // metadata order: x, Wx, Wn, b, neighbor
    const float* x        = (const float*)d_in[0];
    const float* Wx       = (const float*)d_in[1];
    const float* Wn       = (const float*)d_in[2];
    const float* bias     = (const float*)d_in[3];
    const int*   neighbor = (const int*)d_in[4];
    float*       out      = (float*)d_out;

    wfrag_build_kernel<<<8, 256>>>(Wx, Wn);

    gemm_tc_kernel<<<GRID_A, 256>>>(x, bias, out);   // persistent

    dim3 gridB(NV / 32, BATCH);                      // 625 x 16
    gather_add_kernel<<<gridB, 256>>>(neighbor, out);
}